// round 2
// baseline (speedup 1.0000x reference)
#include <cuda_runtime.h>

// SSIM loss, fused single-pass, f32x2-packed:
// separable 11-tap Gaussian blur of {i1, i2, i1^2, i2^2, i1*i2}
// + elementwise SSIM + deterministic mean, all in ONE kernel.
// Inputs: 2x [16,3,512,512] fp32. Output: 1 fp32 scalar.

typedef unsigned long long ull;

#define NTHR    128                  // threads per block
#define TPW     256                  // tile width in pixels (2 per thread)
#define TILE_H  33                   // 3 * 11 -> static ring indices
#define RAD     5
#define KW      11
#define SROWS   (TILE_H + 2 * RAD)   // 43
#define SCOLS   (TPW + 2 * RAD)      // 266 floats (even -> 8B rows)
#define HH      512
#define WW      512
#define PLANES  48                   // 16*3
#define GX      (WW / TPW)           // 2
#define GY      16                   // ceil(512/33), covers 528 rows (masked)
#define NBLK    (GX * GY * PLANES)   // 1536
#define SMEM_BYTES (2 * SROWS * SCOLS * 4)   // 91504

__device__ float        g_partials[NBLK];
__device__ unsigned int g_count = 0;

// ---- f32x2 helpers (Blackwell packed fp32; ptxas never emits these from C++) ----
__device__ __forceinline__ ull F2(float a, float b) {
    ull r; asm("mov.b64 %0,{%1,%2};" : "=l"(r) : "f"(a), "f"(b)); return r;
}
__device__ __forceinline__ void UF2(ull v, float& a, float& b) {
    asm("mov.b64 {%0,%1},%2;" : "=f"(a), "=f"(b) : "l"(v));
}
__device__ __forceinline__ ull FMA2(ull a, ull b, ull c) {
    ull r; asm("fma.rn.f32x2 %0,%1,%2,%3;" : "=l"(r) : "l"(a), "l"(b), "l"(c)); return r;
}
__device__ __forceinline__ ull MUL2(ull a, ull b) {
    ull r; asm("mul.rn.f32x2 %0,%1,%2;" : "=l"(r) : "l"(a), "l"(b)); return r;
}
__device__ __forceinline__ ull ADD2(ull a, ull b) {
    ull r; asm("add.rn.f32x2 %0,%1,%2;" : "=l"(r) : "l"(a), "l"(b)); return r;
}

// Horizontal 11-tap blur of 5 fields for a pixel PAIR (cols 2t, 2t+1) at smem row yi.
__device__ __forceinline__ void hblur(const float* __restrict__ s1,
                                      const float* __restrict__ s2,
                                      int yi, int t, const ull* __restrict__ wk2,
                                      ull& m1, ull& m2, ull& q1, ull& q2, ull& q12)
{
    const float2* __restrict__ p1 = (const float2*)(s1 + yi * SCOLS) + t;
    const float2* __restrict__ p2 = (const float2*)(s2 + yi * SCOLS) + t;
    float2 a[6], b[6];
    #pragma unroll
    for (int j = 0; j < 6; ++j) { a[j] = p1[j]; b[j] = p2[j]; }

    ull A1 = 0, A2 = 0, B1 = 0, B2 = 0, B12 = 0;   // two packed 0.0f
    #pragma unroll
    for (int k = 0; k < KW; ++k) {
        ull va = (k & 1) ? F2(a[k >> 1].y, a[(k >> 1) + 1].x)
                         : F2(a[k >> 1].x, a[k >> 1].y);
        ull vb = (k & 1) ? F2(b[k >> 1].y, b[(k >> 1) + 1].x)
                         : F2(b[k >> 1].x, b[k >> 1].y);
        ull wa = MUL2(wk2[k], va);
        ull wb = MUL2(wk2[k], vb);
        A1  = FMA2(wk2[k], va, A1);
        A2  = FMA2(wk2[k], vb, A2);
        B1  = FMA2(wa, va, B1);
        B2  = FMA2(wb, vb, B2);
        B12 = FMA2(wa, vb, B12);
    }
    m1 = A1; m2 = A2; q1 = B1; q2 = B2; q12 = B12;
}

__global__ void __launch_bounds__(NTHR)
ssim_main(const float* __restrict__ img1, const float* __restrict__ img2,
          float* __restrict__ out)
{
    extern __shared__ float smem[];
    float* s1 = smem;
    float* s2 = smem + SROWS * SCOLS;

    const int t     = threadIdx.x;
    const int x0    = blockIdx.x * TPW;
    const int y0    = blockIdx.y * TILE_H;
    const int plane = blockIdx.z;
    const size_t base = (size_t)plane * (HH * WW);

    // Gaussian weights (sigma=1.5), normalized, packed (broadcast lanes).
    ull wk2[KW];
    {
        float w[KW], s = 0.f;
        #pragma unroll
        for (int k = 0; k < KW; ++k) {
            float d = (float)(k - RAD);
            w[k] = expf(-d * d / (2.f * 1.5f * 1.5f));
            s += w[k];
        }
        float inv = 1.f / s;
        #pragma unroll
        for (int k = 0; k < KW; ++k) wk2[k] = F2(w[k] * inv, w[k] * inv);
    }

    // Cooperative halo'd tile load (zero-pad outside image).
    const int total = SROWS * SCOLS;
    for (int idx = t; idx < total; idx += NTHR) {
        int yy = idx / SCOLS;
        int xx = idx - yy * SCOLS;
        int gy = y0 + yy - RAD;
        int gx = x0 + xx - RAD;
        float v1 = 0.f, v2 = 0.f;
        if (gy >= 0 && gy < HH && gx >= 0 && gx < WW) {
            size_t off = base + (size_t)gy * WW + gx;
            v1 = img1[off];
            v2 = img2[off];
        }
        s1[idx] = v1;
        s2[idx] = v2;
    }
    __syncthreads();

    // Register ring of 5 packed fields, 11 rows deep, static indexing.
    ull rm1[KW], rm2[KW], rq1[KW], rq2[KW], rq12[KW];
    #pragma unroll
    for (int j = 0; j < KW - 1; ++j)
        hblur(s1, s2, j, t, wk2, rm1[j], rm2[j], rq1[j], rq2[j], rq12[j]);

    const ull TWO2 = F2(2.f, 2.f);
    const ull NEG1 = F2(-1.f, -1.f);
    const ull C1v  = F2(1e-4f, 1e-4f);
    const ull C2v  = F2(9e-4f, 9e-4f);
    float acc0 = 0.f, acc1 = 0.f;

    for (int ob = 0; ob < 3; ++ob) {
        #pragma unroll
        for (int u = 0; u < KW; ++u) {
            const int oy = ob * KW + u;
            const int sn = (u + 10) % KW;   // slot of incoming row oy+10
            hblur(s1, s2, oy + 10, t, wk2,
                  rm1[sn], rm2[sn], rq1[sn], rq2[sn], rq12[sn]);

            ull m1 = 0, m2 = 0, q1 = 0, q2 = 0, q12 = 0;
            #pragma unroll
            for (int j = 0; j < KW; ++j) {
                const int s = (u + j) % KW;
                m1  = FMA2(wk2[j], rm1[s],  m1);
                m2  = FMA2(wk2[j], rm2[s],  m2);
                q1  = FMA2(wk2[j], rq1[s],  q1);
                q2  = FMA2(wk2[j], rq2[s],  q2);
                q12 = FMA2(wk2[j], rq12[s], q12);
            }

            // SSIM map (packed, 2 pixels)
            ull mu12 = MUL2(m1, m2);
            ull mu1s = MUL2(m1, m1);
            ull mu2s = MUL2(m2, m2);
            ull s12  = FMA2(mu12, NEG1, q12);        // sigma12
            ull n1   = FMA2(TWO2, mu12, C1v);
            ull n2   = FMA2(TWO2, s12,  C2v);
            ull aa   = ADD2(mu1s, mu2s);
            ull d1   = ADD2(aa, C1v);
            ull qq   = ADD2(q1, q2);
            ull tt   = FMA2(aa, NEG1, qq);           // sigma1^2 + sigma2^2
            ull d2   = ADD2(tt, C2v);
            ull num  = MUL2(n1, n2);
            ull den  = MUL2(d1, d2);

            if (y0 + oy < HH) {
                float nx, ny, dx, dy;
                UF2(num, nx, ny);
                UF2(den, dx, dy);
                acc0 += __fdividef(nx, dx);
                acc1 += __fdividef(ny, dy);
            }
        }
    }

    // Block reduction (deterministic).
    float acc = acc0 + acc1;
    #pragma unroll
    for (int o = 16; o; o >>= 1)
        acc += __shfl_xor_sync(0xFFFFFFFFu, acc, o);

    __shared__ float ws[NTHR / 32];
    if ((t & 31) == 0) ws[t >> 5] = acc;
    __syncthreads();

    const int bid = (blockIdx.z * GY + blockIdx.y) * GX + blockIdx.x;
    __shared__ unsigned int is_last;
    if (t == 0) {
        float bs = 0.f;
        #pragma unroll
        for (int i = 0; i < NTHR / 32; ++i) bs += ws[i];
        __stcg(&g_partials[bid], bs);
        __threadfence();
        is_last = (atomicAdd(&g_count, 1u) == (unsigned)(NBLK - 1));
    }
    __syncthreads();

    // Last finishing block does the final deterministic reduction.
    if (is_last) {
        double s = 0.0;
        for (int i = t; i < NBLK; i += NTHR)
            s += (double)__ldcg(&g_partials[i]);
        #pragma unroll
        for (int o = 16; o; o >>= 1)
            s += __shfl_xor_sync(0xFFFFFFFFu, s, o);
        __shared__ double wd[NTHR / 32];
        if ((t & 31) == 0) wd[t >> 5] = s;
        __syncthreads();
        if (t == 0) {
            double bs = 0.0;
            #pragma unroll
            for (int i = 0; i < NTHR / 32; ++i) bs += wd[i];
            double n = (double)PLANES * HH * WW;
            out[0] = (float)(1.0 - bs / n);
            g_count = 0;   // reset for next graph replay
        }
    }
}

extern "C" void kernel_launch(void* const* d_in, const int* in_sizes, int n_in,
                              void* d_out, int out_size)
{
    (void)in_sizes; (void)n_in; (void)out_size;
    const float* img1 = (const float*)d_in[0];
    const float* img2 = (const float*)d_in[1];
    float* out = (float*)d_out;

    cudaFuncSetAttribute(ssim_main,
                         cudaFuncAttributeMaxDynamicSharedMemorySize, SMEM_BYTES);

    dim3 grid(GX, GY, PLANES);
    ssim_main<<<grid, NTHR, SMEM_BYTES>>>(img1, img2, out);
}

// round 3
// speedup vs baseline: 1.4698x; 1.4698x over previous
#include <cuda_runtime.h>

// SSIM loss, fused single-pass, scalar with IMMEDIATE-form FFMA (rt_SMSP=1):
// separable 11-tap Gaussian blur of {i1, i2, i1^2+i2^2, i1*i2}
// + elementwise SSIM + deterministic mean, one kernel.
// Inputs: 2x [16,3,512,512] fp32. Output: 1 fp32 scalar.

#define NTHR    128
#define TILE_W  128
#define TILE_H  33                   // 3 * 11 -> static ring indices
#define RAD     5
#define KW      11
#define SROWS   (TILE_H + 2 * RAD)   // 43
#define SCOLS   (TILE_W + 2 * RAD)   // 138
#define HH      512
#define WW      512
#define PLANES  48                   // 16*3
#define GX      (WW / TILE_W)        // 4
#define GY      16                   // 16*33 = 528 rows, tail masked
#define NBLK    (GX * GY * PLANES)   // 3072

// Gaussian(sigma=1.5), 11 taps, normalized — compile-time literals so ptxas
// emits FFMA/FMUL with immediate src1 (rt_SMSP=1 instead of 2).
#define W0  0.00102838f
#define W1  0.00759875f
#define W2  0.03600078f
#define W3  0.10936070f
#define W4  0.21300538f
#define W5  0.26601172f
__device__ __constant__ const float GW_[KW] = { // not used in hot loops
    W0, W1, W2, W3, W4, W5, W4, W3, W2, W1, W0 };

__device__ float        g_partials[NBLK];
__device__ unsigned int g_count = 0;

__global__ void __launch_bounds__(NTHR, 4)
ssim_main(const float* __restrict__ img1, const float* __restrict__ img2,
          float* __restrict__ out)
{
    __shared__ float s1[SROWS * SCOLS];
    __shared__ float s2[SROWS * SCOLS];

    const int t     = threadIdx.x;
    const int x0    = blockIdx.x * TILE_W;
    const int y0    = blockIdx.y * TILE_H;
    const int plane = blockIdx.z;
    const size_t base = (size_t)plane * (HH * WW);

    // Cooperative halo'd tile load (zero-pad outside image).
    const int total = SROWS * SCOLS;
    for (int idx = t; idx < total; idx += NTHR) {
        int yy = idx / SCOLS;
        int xx = idx - yy * SCOLS;
        int gy = y0 + yy - RAD;
        int gx = x0 + xx - RAD;
        float v1 = 0.f, v2 = 0.f;
        if (gy >= 0 && gy < HH && gx >= 0 && gx < WW) {
            size_t off = base + (size_t)gy * WW + gx;
            v1 = img1[off];
            v2 = img2[off];
        }
        s1[idx] = v1;
        s2[idx] = v2;
    }
    __syncthreads();

    // Register ring: 4 fields x 11 rows, static indexing (no shifts).
    float rm1[KW], rm2[KW], rqs[KW], rq12[KW];

    // Horizontal 11-tap blur of the 4 fields at smem row yi, cols t..t+10.
    // All weight multiplies use literal constants -> immediate-form FFMA/FMUL.
    auto hblur = [&](int yi, float& om1, float& om2, float& oqs, float& oq12) {
        const float* __restrict__ p1 = &s1[yi * SCOLS + t];
        const float* __restrict__ p2 = &s2[yi * SCOLS + t];
        float m1 = 0.f, m2 = 0.f, qs = 0.f, q12 = 0.f;
        #pragma unroll
        for (int k = 0; k < KW; ++k) {
            const float wk = (k < 6) ? ((k == 0) ? W0 : (k == 1) ? W1 : (k == 2) ? W2
                                      : (k == 3) ? W3 : (k == 4) ? W4 : W5)
                                     : ((k == 6) ? W4 : (k == 7) ? W3 : (k == 8) ? W2
                                      : (k == 9) ? W1 : W0);
            float a  = p1[k];
            float b  = p2[k];
            m1  = fmaf(wk, a, m1);          // FFMA imm
            m2  = fmaf(wk, b, m2);          // FFMA imm
            float wa = wk * a;              // FMUL imm
            float wb = wk * b;              // FMUL imm
            qs  = fmaf(wa, a, qs);
            qs  = fmaf(wb, b, qs);
            q12 = fmaf(wa, b, q12);
        }
        om1 = m1; om2 = m2; oqs = qs; oq12 = q12;
    };

    // Prologue: ring slots 0..9 hold input rows 0..9.
    #pragma unroll
    for (int j = 0; j < KW - 1; ++j)
        hblur(j, rm1[j], rm2[j], rqs[j], rq12[j]);

    const float C1 = 1e-4f;
    const float C2 = 9e-4f;
    float acc = 0.f;

    for (int ob = 0; ob < 3; ++ob) {
        #pragma unroll
        for (int u = 0; u < KW; ++u) {
            const int oy = ob * KW + u;
            const int sn = (u + 10) % KW;     // compile-time slot
            hblur(oy + 10, rm1[sn], rm2[sn], rqs[sn], rq12[sn]);

            // Vertical blur (all imm-form FFMA).
            float m1 = 0.f, m2 = 0.f, qs = 0.f, q12 = 0.f;
            #pragma unroll
            for (int j = 0; j < KW; ++j) {
                const int s = (u + j) % KW;   // compile-time
                const float wj = (j < 6) ? ((j == 0) ? W0 : (j == 1) ? W1 : (j == 2) ? W2
                                          : (j == 3) ? W3 : (j == 4) ? W4 : W5)
                                         : ((j == 6) ? W4 : (j == 7) ? W3 : (j == 8) ? W2
                                          : (j == 9) ? W1 : W0);
                m1  = fmaf(wj, rm1[s],  m1);
                m2  = fmaf(wj, rm2[s],  m2);
                qs  = fmaf(wj, rqs[s],  qs);
                q12 = fmaf(wj, rq12[s], q12);
            }

            // SSIM map value (2 pixels' worth of constants fold as imm too).
            float mu12 = m1 * m2;
            float mu1s = m1 * m1;
            float mu2s = m2 * m2;
            float s12  = q12 - mu12;
            float n1   = fmaf(2.f, mu12, C1);
            float n2   = fmaf(2.f, s12,  C2);
            float tt   = mu1s + mu2s;
            float d1   = tt + C1;
            float d2   = (qs - tt) + C2;
            float v    = __fdividef(n1 * n2, d1 * d2);
            if (y0 + oy < HH) acc += v;

            // no ring shift: indices are static
        }
    }

    // Deterministic block reduction.
    #pragma unroll
    for (int o = 16; o; o >>= 1)
        acc += __shfl_xor_sync(0xFFFFFFFFu, acc, o);

    __shared__ float ws[NTHR / 32];
    if ((t & 31) == 0) ws[t >> 5] = acc;
    __syncthreads();

    const int bid = (blockIdx.z * GY + blockIdx.y) * GX + blockIdx.x;
    __shared__ unsigned int is_last;
    if (t == 0) {
        float bs = 0.f;
        #pragma unroll
        for (int i = 0; i < NTHR / 32; ++i) bs += ws[i];
        __stcg(&g_partials[bid], bs);
        __threadfence();
        is_last = (atomicAdd(&g_count, 1u) == (unsigned)(NBLK - 1));
    }
    __syncthreads();

    // Last finishing block: final deterministic reduction in double.
    if (is_last) {
        double s = 0.0;
        for (int i = t; i < NBLK; i += NTHR)
            s += (double)__ldcg(&g_partials[i]);
        #pragma unroll
        for (int o = 16; o; o >>= 1)
            s += __shfl_xor_sync(0xFFFFFFFFu, s, o);
        __shared__ double wd[NTHR / 32];
        if ((t & 31) == 0) wd[t >> 5] = s;
        __syncthreads();
        if (t == 0) {
            double bs = 0.0;
            #pragma unroll
            for (int i = 0; i < NTHR / 32; ++i) bs += wd[i];
            double n = (double)PLANES * HH * WW;
            out[0] = (float)(1.0 - bs / n);
            g_count = 0;   // reset for next graph replay
        }
    }
}

extern "C" void kernel_launch(void* const* d_in, const int* in_sizes, int n_in,
                              void* d_out, int out_size)
{
    (void)in_sizes; (void)n_in; (void)out_size;
    const float* img1 = (const float*)d_in[0];
    const float* img2 = (const float*)d_in[1];
    float* out = (float*)d_out;

    dim3 grid(GX, GY, PLANES);
    ssim_main<<<grid, NTHR>>>(img1, img2, out);
}

// round 4
// speedup vs baseline: 3.1769x; 2.1615x over previous
#include <cuda_runtime.h>

// SSIM loss, vertical-first separable blur:
//   phase V: thread-per-column vertical 11-tap of {i1,i2,i1^2+i2^2,i1*i2}
//            from GLOBAL (register rings, insert-time squares), -> smem SoA
//   phase H: 4 adjacent px/thread, float4 conflict-free smem reads,
//            horizontal 11-tap + SSIM + deterministic mean (fused last-block).
// Inputs: 2x [16,3,512,512] fp32. Output: 1 fp32 scalar.

#define NTHR    160
#define TILE_W  128
#define TILE_H  16
#define RAD     5
#define KW      11
#define VCOLS   (TILE_W + 2 * RAD)   // 138 columns in vertical phase
#define VSTRIDE 140                  // row stride (floats), 16B-aligned rows
#define HH      512
#define WW      512
#define PLANES  48
#define GX      (WW / TILE_W)        // 4
#define GY      (HH / TILE_H)        // 32
#define NBLK    (GX * GY * PLANES)   // 6144

__device__ float        g_partials[NBLK];
__device__ unsigned int g_count = 0;

// Gaussian(sigma=1.5) 11 taps, normalized; compile-time -> FFMA with immediate.
__device__ __forceinline__ constexpr float GW(int k) {
    return (k == 0 || k == 10) ? 0.00102838f
         : (k == 1 || k == 9)  ? 0.00759877f
         : (k == 2 || k == 8)  ? 0.03600075f
         : (k == 3 || k == 7)  ? 0.10936082f
         : (k == 4 || k == 6)  ? 0.21300554f
         :                       0.26601172f;
}

__global__ void __launch_bounds__(NTHR, 5)
ssim_main(const float* __restrict__ img1, const float* __restrict__ img2,
          float* __restrict__ out)
{
    // SoA field buffers: [field][row][col], rows 16B-aligned.
    __shared__ __align__(16) float smf[4][TILE_H][VSTRIDE];

    const int tid   = threadIdx.x;
    const int x0    = blockIdx.x * TILE_W;
    const int y0    = blockIdx.y * TILE_H;
    const int plane = blockIdx.z;
    const size_t pbase = (size_t)plane * (HH * WW);

    // ================= Vertical phase =================
    if (tid < VCOLS) {
        const int gx  = x0 + tid - RAD;
        const bool vx = ((unsigned)gx < WW);
        const int gxc = min(max(gx, 0), WW - 1);
        const float* __restrict__ p1 = img1 + pbase + gxc;
        const float* __restrict__ p2 = img2 + pbase + gxc;

        float ra[KW], rb[KW], rs[KW], rp[KW];

        auto loadrow = [&](int i, float& a, float& b) {
            int gy = y0 + i - RAD;
            bool ok = vx && ((unsigned)gy < HH);
            int gyc = min(max(gy, 0), HH - 1);
            size_t off = (size_t)gyc * WW;
            a = ok ? __ldg(p1 + off) : 0.f;
            b = ok ? __ldg(p2 + off) : 0.f;
        };

        #pragma unroll
        for (int i = 0; i < KW - 1; ++i) {
            float a, b; loadrow(i, a, b);
            ra[i] = a; rb[i] = b;
            rs[i] = fmaf(b, b, a * a);
            rp[i] = a * b;
        }
        float ca, cb;
        loadrow(KW - 1, ca, cb);   // row index 10

        #pragma unroll
        for (int u = 0; u < TILE_H; ++u) {
            const int sl = (u + KW - 1) % KW;
            ra[sl] = ca; rb[sl] = cb;
            rs[sl] = fmaf(cb, cb, ca * ca);
            rp[sl] = ca * cb;
            if (u < TILE_H - 1) loadrow(u + KW, ca, cb);   // prefetch next row

            float m1 = 0.f, m2 = 0.f, qs = 0.f, q12 = 0.f;
            #pragma unroll
            for (int j = 0; j < KW; ++j) {
                const int s = (u + j) % KW;      // compile-time
                m1  = fmaf(GW(j), ra[s], m1);
                m2  = fmaf(GW(j), rb[s], m2);
                qs  = fmaf(GW(j), rs[s], qs);
                q12 = fmaf(GW(j), rp[s], q12);
            }
            smf[0][u][tid] = m1;
            smf[1][u][tid] = m2;
            smf[2][u][tid] = qs;
            smf[3][u][tid] = q12;
        }
    }
    __syncthreads();

    // ================= Horizontal + SSIM phase =================
    float acc = 0.f;
    if (tid < 128) {
        const int cg = tid & 31;    // column group: output cols 4cg..4cg+3
        const int rg = tid >> 5;    // row offset within groups of 4

        #pragma unroll 1
        for (int rr = 0; rr < 4; ++rr) {
            const int r = rr * 4 + rg;

            float fm1[4], fm2[4], fqs[4], fq12[4];
            #pragma unroll
            for (int d = 0; d < 4; ++d) { fm1[d] = fm2[d] = fqs[d] = fq12[d] = 0.f; }

            // Per field: 4 float4 loads cover cols 4cg..4cg+15 (need ..+13).
            #pragma unroll
            for (int f = 0; f < 4; ++f) {
                const float4* __restrict__ rp4 =
                    reinterpret_cast<const float4*>(&smf[f][r][0]);
                float4 q0 = rp4[cg + 0];
                float4 q1 = rp4[cg + 1];
                float4 q2 = rp4[cg + 2];
                float4 q3 = rp4[cg + 3];
                float cv[16] = { q0.x, q0.y, q0.z, q0.w,
                                 q1.x, q1.y, q1.z, q1.w,
                                 q2.x, q2.y, q2.z, q2.w,
                                 q3.x, q3.y, q3.z, q3.w };
                float* dst = (f == 0) ? fm1 : (f == 1) ? fm2 : (f == 2) ? fqs : fq12;
                #pragma unroll
                for (int d = 0; d < 4; ++d) {
                    float a = 0.f;
                    #pragma unroll
                    for (int k = 0; k < KW; ++k)
                        a = fmaf(GW(k), cv[d + k], a);
                    dst[d] = a;
                }
            }

            #pragma unroll
            for (int d = 0; d < 4; ++d) {
                float mu12 = fm1[d] * fm2[d];
                float mu1s = fm1[d] * fm1[d];
                float mu2s = fm2[d] * fm2[d];
                float s12  = fq12[d] - mu12;
                float n1   = fmaf(2.f, mu12, 1e-4f);
                float n2   = fmaf(2.f, s12,  9e-4f);
                float ttv  = mu1s + mu2s;
                float d1   = ttv + 1e-4f;
                float d2   = (fqs[d] - ttv) + 9e-4f;
                acc += __fdividef(n1 * n2, d1 * d2);
            }
        }
    }

    // ================= Reduction =================
    #pragma unroll
    for (int o = 16; o; o >>= 1)
        acc += __shfl_xor_sync(0xFFFFFFFFu, acc, o);

    __shared__ float ws[NTHR / 32];
    if ((tid & 31) == 0) ws[tid >> 5] = acc;
    __syncthreads();

    const int bid = (blockIdx.z * GY + blockIdx.y) * GX + blockIdx.x;
    __shared__ unsigned int is_last;
    if (tid == 0) {
        float bs = 0.f;
        #pragma unroll
        for (int i = 0; i < NTHR / 32; ++i) bs += ws[i];
        __stcg(&g_partials[bid], bs);
        __threadfence();
        is_last = (atomicAdd(&g_count, 1u) == (unsigned)(NBLK - 1));
    }
    __syncthreads();

    if (is_last) {
        double s = 0.0;
        for (int i = tid; i < NBLK; i += NTHR)
            s += (double)__ldcg(&g_partials[i]);
        #pragma unroll
        for (int o = 16; o; o >>= 1)
            s += __shfl_xor_sync(0xFFFFFFFFu, s, o);
        __shared__ double wd[NTHR / 32];
        if ((tid & 31) == 0) wd[tid >> 5] = s;
        __syncthreads();
        if (tid == 0) {
            double bs = 0.0;
            #pragma unroll
            for (int i = 0; i < NTHR / 32; ++i) bs += wd[i];
            double n = (double)PLANES * HH * WW;
            out[0] = (float)(1.0 - bs / n);
            g_count = 0;   // reset for next graph replay
        }
    }
}

extern "C" void kernel_launch(void* const* d_in, const int* in_sizes, int n_in,
                              void* d_out, int out_size)
{
    (void)in_sizes; (void)n_in; (void)out_size;
    const float* img1 = (const float*)d_in[0];
    const float* img2 = (const float*)d_in[1];
    float* out = (float*)d_out;

    dim3 grid(GX, GY, PLANES);
    ssim_main<<<grid, NTHR>>>(img1, img2, out);
}

// round 5
// speedup vs baseline: 3.2908x; 1.0359x over previous
#include <cuda_runtime.h>

// SSIM loss, vertical-first separable blur with f32x2 packing:
//   V: thread-per-column, FIELD-packed rings (a,b) / (a^2+b^2, ab) -> 22 FMA2/row
//   H: 4 px/thread, PIXEL-PAIR packed taps -> 22 FMA2/px, packed SSIM
// Inputs: 2x [16,3,512,512] fp32. Output: 1 fp32 scalar.

typedef unsigned long long ull;

#define NTHR    160
#define TILE_W  128
#define TILE_H  16
#define RAD     5
#define KW      11
#define VCOLS   (TILE_W + 2 * RAD)   // 138
#define VSTRIDE 140                  // floats per row, 16B aligned
#define HH      512
#define WW      512
#define PLANES  48
#define GX      (WW / TILE_W)        // 4
#define GY      (HH / TILE_H)        // 32
#define NBLK    (GX * GY * PLANES)   // 6144

__device__ float        g_partials[NBLK];
__device__ unsigned int g_count = 0;

// Gaussian(sigma=1.5) 11 taps, normalized.
__device__ __forceinline__ constexpr float GW(int k) {
    return (k == 0 || k == 10) ? 0.00102838f
         : (k == 1 || k == 9)  ? 0.00759877f
         : (k == 2 || k == 8)  ? 0.03600075f
         : (k == 3 || k == 7)  ? 0.10936082f
         : (k == 4 || k == 6)  ? 0.21300554f
         :                       0.26601172f;
}

// ---- f32x2 helpers ----
__device__ __forceinline__ ull F2(float a, float b) {
    ull r; asm("mov.b64 %0,{%1,%2};" : "=l"(r) : "f"(a), "f"(b)); return r;
}
__device__ __forceinline__ float FLO(ull v) {
    float a, b; asm("mov.b64 {%0,%1},%2;" : "=f"(a), "=f"(b) : "l"(v)); return a;
}
__device__ __forceinline__ float FHI(ull v) {
    float a, b; asm("mov.b64 {%0,%1},%2;" : "=f"(a), "=f"(b) : "l"(v)); return b;
}
__device__ __forceinline__ ull FMA2(ull a, ull b, ull c) {
    ull r; asm("fma.rn.f32x2 %0,%1,%2,%3;" : "=l"(r) : "l"(a), "l"(b), "l"(c)); return r;
}
__device__ __forceinline__ ull MUL2(ull a, ull b) {
    ull r; asm("mul.rn.f32x2 %0,%1,%2;" : "=l"(r) : "l"(a), "l"(b)); return r;
}
__device__ __forceinline__ ull ADD2(ull a, ull b) {
    ull r; asm("add.rn.f32x2 %0,%1,%2;" : "=l"(r) : "l"(a), "l"(b)); return r;
}

__global__ void __launch_bounds__(NTHR, 5)
ssim_main(const float* __restrict__ img1, const float* __restrict__ img2,
          float* __restrict__ out)
{
    __shared__ __align__(16) float smf[4][TILE_H][VSTRIDE];

    const int tid   = threadIdx.x;
    const int x0    = blockIdx.x * TILE_W;
    const int y0    = blockIdx.y * TILE_H;
    const int plane = blockIdx.z;
    const size_t pbase = (size_t)plane * (HH * WW);

    // 6 distinct packed weights (symmetric kernel).
    ull w2[6];
    #pragma unroll
    for (int k = 0; k < 6; ++k) w2[k] = F2(GW(k), GW(k));

    // ================= Vertical phase (field-packed f32x2) =================
    if (tid < VCOLS) {
        const int gx  = x0 + tid - RAD;
        const bool vx = ((unsigned)gx < WW);
        const int gxc = min(max(gx, 0), WW - 1);
        const float* __restrict__ p1 = img1 + pbase + gxc;
        const float* __restrict__ p2 = img2 + pbase + gxc;

        ull rab[KW];   // (a, b)
        ull rsp[KW];   // (a^2+b^2, a*b)
        float ca, cb;

        auto loadrow = [&](int i, float& a, float& b) {
            int gy = y0 + i - RAD;
            bool ok = vx && ((unsigned)gy < HH);
            int gyc = min(max(gy, 0), HH - 1);
            size_t off = (size_t)gyc * WW;
            a = ok ? __ldg(p1 + off) : 0.f;
            b = ok ? __ldg(p2 + off) : 0.f;
        };

        #pragma unroll
        for (int i = 0; i < KW - 1; ++i) {
            float a, b; loadrow(i, a, b);
            rab[i] = F2(a, b);
            rsp[i] = F2(fmaf(a, a, b * b), a * b);
        }
        loadrow(KW - 1, ca, cb);

        #pragma unroll
        for (int u = 0; u < TILE_H; ++u) {
            const int sl = (u + KW - 1) % KW;
            rab[sl] = F2(ca, cb);
            rsp[sl] = F2(fmaf(ca, ca, cb * cb), ca * cb);
            if (u < TILE_H - 1) loadrow(u + KW, ca, cb);

            ull m = 0, q = 0;   // (m1,m2), (qs,q12)
            #pragma unroll
            for (int j = 0; j < KW; ++j) {
                const int s = (u + j) % KW;            // compile-time
                const ull wj = w2[(j < 6) ? j : 10 - j];
                m = FMA2(wj, rab[s], m);
                q = FMA2(wj, rsp[s], q);
            }
            smf[0][u][tid] = FLO(m);
            smf[1][u][tid] = FHI(m);
            smf[2][u][tid] = FLO(q);
            smf[3][u][tid] = FHI(q);
        }
    }
    __syncthreads();

    // ================= Horizontal + SSIM (pixel-pair f32x2) =================
    float acc = 0.f;
    if (tid < 128) {
        const int cg = tid & 31;    // output cols 4cg..4cg+3
        const int rg = tid >> 5;    // row slot

        const ull NEG1 = F2(-1.f, -1.f);
        const ull TWO2 = F2(2.f, 2.f);
        const ull C1v  = F2(1e-4f, 1e-4f);
        const ull C2v  = F2(9e-4f, 9e-4f);

        #pragma unroll 1
        for (int rr = 0; rr < 4; ++rr) {
            const int r = rr * 4 + rg;

            ull am1[2] = {0, 0}, am2[2] = {0, 0}, aqs[2] = {0, 0}, aq12[2] = {0, 0};

            #pragma unroll
            for (int f = 0; f < 4; ++f) {
                const float4* __restrict__ rp4 =
                    reinterpret_cast<const float4*>(&smf[f][r][0]);
                float4 q0 = rp4[cg + 0];
                float4 q1 = rp4[cg + 1];
                float4 q2 = rp4[cg + 2];
                float4 q3 = rp4[cg + 3];
                float cv[16] = { q0.x, q0.y, q0.z, q0.w,
                                 q1.x, q1.y, q1.z, q1.w,
                                 q2.x, q2.y, q2.z, q2.w,
                                 q3.x, q3.y, q3.z, q3.w };
                ull* dst = (f == 0) ? am1 : (f == 1) ? am2 : (f == 2) ? aqs : aq12;

                #pragma unroll
                for (int p = 0; p < 2; ++p) {          // pixel pairs (0,1) and (2,3)
                    ull a = dst[p];
                    #pragma unroll
                    for (int k = 0; k < KW; ++k) {
                        const ull wj = w2[(k < 6) ? k : 10 - k];
                        a = FMA2(wj, F2(cv[2 * p + k], cv[2 * p + k + 1]), a);
                    }
                    dst[p] = a;
                }
            }

            #pragma unroll
            for (int p = 0; p < 2; ++p) {
                ull mu12 = MUL2(am1[p], am2[p]);
                ull mu1s = MUL2(am1[p], am1[p]);
                ull mu2s = MUL2(am2[p], am2[p]);
                ull s12  = FMA2(mu12, NEG1, aq12[p]);  // q12 - mu1*mu2
                ull n1   = FMA2(TWO2, mu12, C1v);
                ull n2   = FMA2(TWO2, s12,  C2v);
                ull aa   = ADD2(mu1s, mu2s);
                ull d1   = ADD2(aa, C1v);
                ull tt   = FMA2(aa, NEG1, aqs[p]);     // qs - (mu1^2+mu2^2)
                ull d2   = ADD2(tt, C2v);
                ull num  = MUL2(n1, n2);
                ull den  = MUL2(d1, d2);
                acc += __fdividef(FLO(num), FLO(den));
                acc += __fdividef(FHI(num), FHI(den));
            }
        }
    }

    // ================= Reduction =================
    #pragma unroll
    for (int o = 16; o; o >>= 1)
        acc += __shfl_xor_sync(0xFFFFFFFFu, acc, o);

    __shared__ float ws[NTHR / 32];
    if ((tid & 31) == 0) ws[tid >> 5] = acc;
    __syncthreads();

    const int bid = (blockIdx.z * GY + blockIdx.y) * GX + blockIdx.x;
    __shared__ unsigned int is_last;
    if (tid == 0) {
        float bs = 0.f;
        #pragma unroll
        for (int i = 0; i < NTHR / 32; ++i) bs += ws[i];
        __stcg(&g_partials[bid], bs);
        __threadfence();
        is_last = (atomicAdd(&g_count, 1u) == (unsigned)(NBLK - 1));
    }
    __syncthreads();

    if (is_last) {
        double s = 0.0;
        for (int i = tid; i < NBLK; i += NTHR)
            s += (double)__ldcg(&g_partials[i]);
        #pragma unroll
        for (int o = 16; o; o >>= 1)
            s += __shfl_xor_sync(0xFFFFFFFFu, s, o);
        __shared__ double wd[NTHR / 32];
        if ((tid & 31) == 0) wd[tid >> 5] = s;
        __syncthreads();
        if (tid == 0) {
            double bs = 0.0;
            #pragma unroll
            for (int i = 0; i < NTHR / 32; ++i) bs += wd[i];
            double n = (double)PLANES * HH * WW;
            out[0] = (float)(1.0 - bs / n);
            g_count = 0;   // reset for next graph replay
        }
    }
}

extern "C" void kernel_launch(void* const* d_in, const int* in_sizes, int n_in,
                              void* d_out, int out_size)
{
    (void)in_sizes; (void)n_in; (void)out_size;
    const float* img1 = (const float*)d_in[0];
    const float* img2 = (const float*)d_in[1];
    float* out = (float*)d_out;

    dim3 grid(GX, GY, PLANES);
    ssim_main<<<grid, NTHR>>>(img1, img2, out);
}